// round 5
// baseline (speedup 1.0000x reference)
#include <cuda_runtime.h>
#include <math.h>

#define NCAM 6
#define CF   128
#define HF   32
#define WF   88
#define PP   4
#define HB   160
#define WB   160
#define QQ   (HB*WB)          // 25600
#define MROWS QQ
#define KDIM 512              // P*C
#define MIDW 256
#define EDIM 128
#define IMGW 704.0f
#define IMGH 256.0f
#define EPSF 1e-5f

// ---- scratch (static device globals; no runtime allocation) ----
__device__ float g_fmap[NCAM*HF*WF*CF];   // feat channel-last   8.6 MB
__device__ float g_x   [MROWS*KDIM];      // sampled+PE features 52 MB  (also viewed as [102400][128])
__device__ float g_y1  [MROWS*KDIM];      // conv1 out           52 MB
__device__ float g_y2  [MROWS*EDIM];      // conv2 out           13 MB
__device__ float g_mean1[KDIM];
__device__ float g_inv1 [KDIM];
__device__ float g_mean2[EDIM];
__device__ float g_inv2 [EDIM];

// ============================================================
// 0) transpose feat [N,C,H,W] -> fmap [N,H,W,C]
// ============================================================
__global__ void k_transpose(const float* __restrict__ feat){
    int idx = blockIdx.x*blockDim.x + threadIdx.x;
    const int total = NCAM*HF*WF*CF;
    if (idx >= total) return;
    int c = idx & (CF-1);
    int rest = idx >> 7;          // CF=128
    int w = rest % WF;
    rest /= WF;
    int h = rest % HF;
    int n = rest / HF;
    g_fmap[idx] = feat[((n*CF + c)*HF + h)*WF + w];
}

// ============================================================
// 1) projection + bilinear sampling.  One warp per (q,p) row,
//    each lane owns 4 channels (float4). Writes g_x row qp=q*4+p.
// ============================================================
__global__ void k_sample(const float* __restrict__ bev, const float* __restrict__ l2i){
    __shared__ float sL[NCAM*16];
    int tid = threadIdx.x;
    if (tid < NCAM*16) sL[tid] = l2i[tid];
    __syncthreads();
    int gw   = (blockIdx.x*blockDim.x + tid) >> 5;
    int lane = tid & 31;
    if (gw >= QQ*PP) return;
    int q = gw >> 2, p = gw & 3;
    const float* bp = bev + (p*QQ + q)*3;
    float rx = bp[0]*100.0f - 50.0f;
    float ry = bp[1]*100.0f - 50.0f;
    float rz = bp[2]*8.0f   - 4.0f;
    float4 acc = make_float4(0.f,0.f,0.f,0.f);
    #pragma unroll
    for (int n=0;n<NCAM;n++){
        const float* L = sL + n*16;
        float c0 = L[0]*rx + L[1]*ry + L[2]*rz  + L[3];
        float c1 = L[4]*rx + L[5]*ry + L[6]*rz  + L[7];
        float hm = L[8]*rx + L[9]*ry + L[10]*rz + L[11];
        float z  = fmaxf(hm, EPSF);
        float u  = (c0 / z) / IMGW;
        float v  = (c1 / z) / IMGH;
        if (!(hm > EPSF && u > 0.f && u < 1.f && v > 0.f && v < 1.f)) continue;
        float x = u*(float)WF - 0.5f;
        float y = v*(float)HF - 0.5f;
        float x0f = floorf(x), y0f = floorf(y);
        float dx = x - x0f,    dy = y - y0f;
        int x0 = (int)x0f,     y0 = (int)y0f;
        float ws[4] = {(1.f-dx)*(1.f-dy), dx*(1.f-dy), (1.f-dx)*dy, dx*dy};
        int   xs[4] = {x0, x0+1, x0,   x0+1};
        int   ys[4] = {y0, y0,   y0+1, y0+1};
        const float* base = g_fmap + (size_t)n*HF*WF*CF;
        #pragma unroll
        for (int cr=0; cr<4; cr++){
            int xi = xs[cr], yi = ys[cr];
            if (xi >= 0 && xi < WF && yi >= 0 && yi < HF){
                float4 vq = reinterpret_cast<const float4*>(base + (yi*WF + xi)*CF)[lane];
                float wq = ws[cr];
                acc.x = fmaf(wq, vq.x, acc.x);
                acc.y = fmaf(wq, vq.y, acc.y);
                acc.z = fmaf(wq, vq.z, acc.z);
                acc.w = fmaf(wq, vq.w, acc.w);
            }
        }
    }
    reinterpret_cast<float4*>(g_x)[gw*32 + lane] = acc;
}

// ============================================================
// 2) PE MLP 3->256->256->128 fused per block of 16 rows;
//    adds result into g_x (viewed as [102400][128]).
//    h tiles stored [k][r] so the inner reads are float4 broadcasts.
// ============================================================
__global__ void k_pe(const float* __restrict__ bev,
                     const float* __restrict__ w1, const float* __restrict__ b1,
                     const float* __restrict__ w2, const float* __restrict__ b2,
                     const float* __restrict__ w3, const float* __restrict__ b3){
    __shared__ float refS[16][3];
    __shared__ float h1s[MIDW][16];   // 16 KB, [j][r]
    __shared__ float h2s[MIDW][16];   // 16 KB, [j][r]
    int tid  = threadIdx.x;
    int row0 = blockIdx.x * 16;
    if (tid < 48){
        int r = tid / 3, d = tid % 3;
        int qp = row0 + r;
        int q = qp >> 2, p = qp & 3;
        refS[r][d] = bev[(p*QQ + q)*3 + d];
    }
    __syncthreads();

    // --- layer 1: h1[j][r] = relu(ref . w1[:,j] + b1[j]) ---
    {
        int r  = tid & 15;
        int jo = tid >> 4;
        float a0 = refS[r][0], a1 = refS[r][1], a2 = refS[r][2];
        #pragma unroll
        for (int pass=0; pass<16; pass++){
            int j = pass*16 + jo;
            float h = b1[j] + a0*w1[j] + a1*w1[MIDW + j] + a2*w1[2*MIDW + j];
            h1s[j][r] = fmaxf(h, 0.f);   // coalesced: addr = pass*256 + tid
        }
    }
    __syncthreads();

    // --- layer 2: each thread = one output column over 16 rows ---
    float acc[16];
    #pragma unroll
    for (int r=0;r<16;r++) acc[r]=0.f;
    #pragma unroll 2
    for (int k=0;k<MIDW;k++){
        float wv = w2[k*MIDW + tid];
        const float4* hr = reinterpret_cast<const float4*>(&h1s[k][0]);
        float4 h0=hr[0], h1v=hr[1], h2v=hr[2], h3v=hr[3];
        acc[0] = fmaf(h0.x ,wv,acc[0]);  acc[1] = fmaf(h0.y ,wv,acc[1]);
        acc[2] = fmaf(h0.z ,wv,acc[2]);  acc[3] = fmaf(h0.w ,wv,acc[3]);
        acc[4] = fmaf(h1v.x,wv,acc[4]);  acc[5] = fmaf(h1v.y,wv,acc[5]);
        acc[6] = fmaf(h1v.z,wv,acc[6]);  acc[7] = fmaf(h1v.w,wv,acc[7]);
        acc[8] = fmaf(h2v.x,wv,acc[8]);  acc[9] = fmaf(h2v.y,wv,acc[9]);
        acc[10]= fmaf(h2v.z,wv,acc[10]); acc[11]= fmaf(h2v.w,wv,acc[11]);
        acc[12]= fmaf(h3v.x,wv,acc[12]); acc[13]= fmaf(h3v.y,wv,acc[13]);
        acc[14]= fmaf(h3v.z,wv,acc[14]); acc[15]= fmaf(h3v.w,wv,acc[15]);
    }
    float bv2 = b2[tid];
    __syncthreads();
    #pragma unroll
    for (int rr=0; rr<4; rr++){
        float4 hv;
        hv.x = fmaxf(acc[rr*4+0]+bv2, 0.f);
        hv.y = fmaxf(acc[rr*4+1]+bv2, 0.f);
        hv.z = fmaxf(acc[rr*4+2]+bv2, 0.f);
        hv.w = fmaxf(acc[rr*4+3]+bv2, 0.f);
        *reinterpret_cast<float4*>(&h2s[tid][rr*4]) = hv;
    }
    __syncthreads();

    // --- layer 3: 128 cols, 2 row-halves of 8 ---
    {
        int col = tid & 127;
        int rh  = tid >> 7;    // 0 or 1
        float a2c[8];
        #pragma unroll
        for (int r=0;r<8;r++) a2c[r]=0.f;
        #pragma unroll 2
        for (int k=0;k<MIDW;k++){
            float wv = w3[k*EDIM + col];
            const float4* hr = reinterpret_cast<const float4*>(&h2s[k][rh*8]);
            float4 h0=hr[0], h1v=hr[1];
            a2c[0]=fmaf(h0.x ,wv,a2c[0]); a2c[1]=fmaf(h0.y ,wv,a2c[1]);
            a2c[2]=fmaf(h0.z ,wv,a2c[2]); a2c[3]=fmaf(h0.w ,wv,a2c[3]);
            a2c[4]=fmaf(h1v.x,wv,a2c[4]); a2c[5]=fmaf(h1v.y,wv,a2c[5]);
            a2c[6]=fmaf(h1v.z,wv,a2c[6]); a2c[7]=fmaf(h1v.w,wv,a2c[7]);
        }
        float bv3 = b3[col];
        #pragma unroll
        for (int r=0;r<8;r++){
            int row = row0 + rh*8 + r;
            g_x[(size_t)row*EDIM + col] += a2c[r] + bv3;
        }
    }
}

// ============================================================
// 3) GEMM: C[m][n] = bias[n] + sum_k f(A[m][k]) * W[n*K+k]
//    64x64 tile, 16-deep K chunks, 4x4 per thread.
//    AMODE=1: f = gelu(instance-norm); OMODE=1: write C transposed [n][m].
// ============================================================
__device__ __forceinline__ float gelu_f(float x){
    return 0.5f * x * (1.0f + erff(x * 0.70710678118654752440f));
}

template<int K, int N, int AMODE, int OMODE>
__device__ __forceinline__ void gemm_body(
    const float* __restrict__ A, const float* __restrict__ W,
    const float* __restrict__ bias, const float* __restrict__ mean,
    const float* __restrict__ inv, float* __restrict__ C)
{
    __shared__ float As[16][64];
    __shared__ float Bs[16][64];
    int tid = threadIdx.x;
    int m0 = blockIdx.x * 64;
    int n0 = blockIdx.y * 64;
    int tx = tid & 15, ty = tid >> 4;
    int ldm = tid >> 2;
    int ldk = (tid & 3) << 2;
    float acc[4][4];
    #pragma unroll
    for (int i=0;i<4;i++)
        #pragma unroll
        for (int j=0;j<4;j++) acc[i][j]=0.f;

    for (int k0=0; k0<K; k0+=16){
        float4 av = *reinterpret_cast<const float4*>(A + (size_t)(m0+ldm)*K + k0 + ldk);
        if (AMODE){
            int kb = k0 + ldk;
            av.x = gelu_f((av.x - mean[kb  ]) * inv[kb  ]);
            av.y = gelu_f((av.y - mean[kb+1]) * inv[kb+1]);
            av.z = gelu_f((av.z - mean[kb+2]) * inv[kb+2]);
            av.w = gelu_f((av.w - mean[kb+3]) * inv[kb+3]);
        }
        As[ldk  ][ldm]=av.x; As[ldk+1][ldm]=av.y; As[ldk+2][ldm]=av.z; As[ldk+3][ldm]=av.w;
        float4 bv = *reinterpret_cast<const float4*>(W + (size_t)(n0+ldm)*K + k0 + ldk);
        Bs[ldk  ][ldm]=bv.x; Bs[ldk+1][ldm]=bv.y; Bs[ldk+2][ldm]=bv.z; Bs[ldk+3][ldm]=bv.w;
        __syncthreads();
        #pragma unroll
        for (int kk=0;kk<16;kk++){
            float4 a4 = *reinterpret_cast<const float4*>(&As[kk][ty<<2]);
            float4 b4 = *reinterpret_cast<const float4*>(&Bs[kk][tx<<2]);
            acc[0][0]=fmaf(a4.x,b4.x,acc[0][0]); acc[0][1]=fmaf(a4.x,b4.y,acc[0][1]);
            acc[0][2]=fmaf(a4.x,b4.z,acc[0][2]); acc[0][3]=fmaf(a4.x,b4.w,acc[0][3]);
            acc[1][0]=fmaf(a4.y,b4.x,acc[1][0]); acc[1][1]=fmaf(a4.y,b4.y,acc[1][1]);
            acc[1][2]=fmaf(a4.y,b4.z,acc[1][2]); acc[1][3]=fmaf(a4.y,b4.w,acc[1][3]);
            acc[2][0]=fmaf(a4.z,b4.x,acc[2][0]); acc[2][1]=fmaf(a4.z,b4.y,acc[2][1]);
            acc[2][2]=fmaf(a4.z,b4.z,acc[2][2]); acc[2][3]=fmaf(a4.z,b4.w,acc[2][3]);
            acc[3][0]=fmaf(a4.w,b4.x,acc[3][0]); acc[3][1]=fmaf(a4.w,b4.y,acc[3][1]);
            acc[3][2]=fmaf(a4.w,b4.z,acc[3][2]); acc[3][3]=fmaf(a4.w,b4.w,acc[3][3]);
        }
        __syncthreads();
    }

    if (OMODE==0){
        float b0 = bias[n0+(tx<<2)+0], b1v = bias[n0+(tx<<2)+1];
        float b2v = bias[n0+(tx<<2)+2], b3v = bias[n0+(tx<<2)+3];
        #pragma unroll
        for (int i=0;i<4;i++){
            int m = m0 + (ty<<2) + i;
            float4 r = make_float4(acc[i][0]+b0, acc[i][1]+b1v, acc[i][2]+b2v, acc[i][3]+b3v);
            *reinterpret_cast<float4*>(C + (size_t)m*N + n0 + (tx<<2)) = r;
        }
    } else {
        #pragma unroll
        for (int j=0;j<4;j++){
            int n = n0 + (tx<<2) + j;
            float bv = bias[n];
            float4 r = make_float4(acc[0][j]+bv, acc[1][j]+bv, acc[2][j]+bv, acc[3][j]+bv);
            *reinterpret_cast<float4*>(C + (size_t)n*MROWS + m0 + (ty<<2)) = r;
        }
    }
}

__global__ void k_gemm1(const float* __restrict__ W, const float* __restrict__ b){
    gemm_body<512,512,0,0>(g_x, W, b, nullptr, nullptr, g_y1);
}
__global__ void k_gemm2(const float* __restrict__ W, const float* __restrict__ b){
    gemm_body<512,128,1,0>(g_y1, W, b, g_mean1, g_inv1, g_y2);
}
__global__ void k_gemm3(const float* __restrict__ W, const float* __restrict__ b, float* __restrict__ out){
    gemm_body<128,128,1,1>(g_y2, W, b, g_mean2, g_inv2, out);
}

// ============================================================
// 4) InstanceNorm stats: per-channel mean + rsqrt(var+eps).
//    One block per 8 channels; thread = (channel, m-lane of 32).
// ============================================================
template<int NCH>
__device__ __forceinline__ void stats_body(const float* __restrict__ Y,
                                           float* __restrict__ meanO, float* __restrict__ invO){
    int tid = threadIdx.x;                 // 256
    int c   = blockIdx.x*8 + (tid & 7);
    int ml  = tid >> 3;                    // 0..31
    float s = 0.f, s2 = 0.f;
    for (int m = ml; m < MROWS; m += 32){
        float v = Y[(size_t)m*NCH + c];
        s  += v;
        s2 = fmaf(v, v, s2);
    }
    __shared__ float ss[256], ss2[256];
    ss[tid] = s; ss2[tid] = s2;
    __syncthreads();
    #pragma unroll
    for (int st=128; st>=8; st>>=1){
        if (tid < st){ ss[tid]+=ss[tid+st]; ss2[tid]+=ss2[tid+st]; }
        __syncthreads();
    }
    if (tid < 8){
        float mean = ss[tid] / (float)MROWS;
        float var  = ss2[tid] / (float)MROWS - mean*mean;
        meanO[c] = mean;
        invO[c]  = rsqrtf(var + 1e-5f);
    }
}
__global__ void k_stats1(){ stats_body<KDIM>(g_y1, g_mean1, g_inv1); }
__global__ void k_stats2(){ stats_body<EDIM>(g_y2, g_mean2, g_inv2); }

// ============================================================
// host entry
// ============================================================
extern "C" void kernel_launch(void* const* d_in, const int* in_sizes, int n_in,
                              void* d_out, int out_size){
    const float* feat = (const float*)d_in[0];
    const float* l2i  = (const float*)d_in[1];
    const float* bev  = (const float*)d_in[2];
    const float* w1   = (const float*)d_in[3];
    const float* b1   = (const float*)d_in[4];
    const float* w2   = (const float*)d_in[5];
    const float* b2   = (const float*)d_in[6];
    const float* w3   = (const float*)d_in[7];
    const float* b3   = (const float*)d_in[8];
    const float* c1w  = (const float*)d_in[9];
    const float* c1b  = (const float*)d_in[10];
    const float* c2w  = (const float*)d_in[11];
    const float* c2b  = (const float*)d_in[12];
    const float* c3w  = (const float*)d_in[13];
    const float* c3b  = (const float*)d_in[14];
    float* out = (float*)d_out;

    k_transpose<<<(NCAM*HF*WF*CF + 255)/256, 256>>>(feat);
    k_sample  <<<(QQ*PP)/8, 256>>>(bev, l2i);
    k_pe      <<<(QQ*PP)/16, 256>>>(bev, w1,b1, w2,b2, w3,b3);
    k_gemm1   <<<dim3(MROWS/64, KDIM/64), 256>>>(c1w, c1b);
    k_stats1  <<<KDIM/8, 256>>>();
    k_gemm2   <<<dim3(MROWS/64, EDIM/64), 256>>>(c2w, c2b);
    k_stats2  <<<EDIM/8, 256>>>();
    k_gemm3   <<<dim3(MROWS/64, EDIM/64), 256>>>(c3w, c3b, out);
}

// round 6
// speedup vs baseline: 2.0780x; 2.0780x over previous
#include <cuda_runtime.h>
#include <cuda_bf16.h>
#include <math.h>
#include <stdint.h>

#define NCAM 6
#define CF   128
#define HF   32
#define WF   88
#define PP   4
#define HB   160
#define WB   160
#define QQ   (HB*WB)          // 25600
#define MROWS QQ
#define MR2   (QQ*PP)         // 102400 (pe rows)
#define KDIM 512              // P*C
#define MIDW 256
#define EDIM 128
#define IMGW 704.0f
#define IMGH 256.0f
#define EPSF 1e-5f

// ---- scratch (static device globals; no runtime allocation) ----
__device__ float g_fmap[NCAM*HF*WF*CF];
__device__ float g_x   [MROWS*KDIM];                    // sampled + PE (fp32)
__device__ float g_y1  [MROWS*KDIM];
__device__ float g_y2  [MROWS*EDIM];
__device__ float g_mean1[KDIM];
__device__ float g_inv1 [KDIM];
__device__ float g_mean2[EDIM];
__device__ float g_inv2 [EDIM];

// bf16 hi/lo operand buffers
__device__ __align__(16) __nv_bfloat16 g_h1h[MR2*MIDW], g_h1l[MR2*MIDW];
__device__ __align__(16) __nv_bfloat16 g_h2h[MR2*MIDW], g_h2l[MR2*MIDW];
__device__ __align__(16) __nv_bfloat16 g_xh [MROWS*KDIM], g_xl [MROWS*KDIM];
__device__ __align__(16) __nv_bfloat16 g_a2h[MROWS*KDIM], g_a2l[MROWS*KDIM];
__device__ __align__(16) __nv_bfloat16 g_a3h[MROWS*EDIM], g_a3l[MROWS*EDIM];
// weights hi/lo ([n][k] layout)
__device__ __align__(16) __nv_bfloat16 g_c1h[KDIM*KDIM],  g_c1l[KDIM*KDIM];
__device__ __align__(16) __nv_bfloat16 g_c2h[EDIM*KDIM],  g_c2l[EDIM*KDIM];
__device__ __align__(16) __nv_bfloat16 g_c3h[EDIM*EDIM],  g_c3l[EDIM*EDIM];
__device__ __align__(16) __nv_bfloat16 g_w2h[MIDW*MIDW],  g_w2l[MIDW*MIDW];
__device__ __align__(16) __nv_bfloat16 g_w3h[EDIM*MIDW],  g_w3l[EDIM*MIDW];

__device__ __forceinline__ void split2(float v, __nv_bfloat16 &h, __nv_bfloat16 &l){
    h = __float2bfloat16(v);
    l = __float2bfloat16(v - __bfloat162float(h));
}
__device__ __forceinline__ float gelu_f(float x){
    return 0.5f * x * (1.0f + erff(x * 0.70710678118654752440f));
}

// ============================================================
// 0) transpose feat [N,C,H,W] -> fmap [N,H,W,C]
// ============================================================
__global__ void k_transpose(const float* __restrict__ feat){
    int idx = blockIdx.x*blockDim.x + threadIdx.x;
    const int total = NCAM*HF*WF*CF;
    if (idx >= total) return;
    int c = idx & (CF-1);
    int rest = idx >> 7;
    int w = rest % WF;
    rest /= WF;
    int h = rest % HF;
    int n = rest / HF;
    g_fmap[idx] = feat[((n*CF + c)*HF + h)*WF + w];
}

// ============================================================
// 1) projection + bilinear sampling -> g_x (fp32)
// ============================================================
__global__ void k_sample(const float* __restrict__ bev, const float* __restrict__ l2i){
    __shared__ float sL[NCAM*16];
    int tid = threadIdx.x;
    if (tid < NCAM*16) sL[tid] = l2i[tid];
    __syncthreads();
    int gw   = (blockIdx.x*blockDim.x + tid) >> 5;
    int lane = tid & 31;
    if (gw >= QQ*PP) return;
    int q = gw >> 2, p = gw & 3;
    const float* bp = bev + (p*QQ + q)*3;
    float rx = bp[0]*100.0f - 50.0f;
    float ry = bp[1]*100.0f - 50.0f;
    float rz = bp[2]*8.0f   - 4.0f;
    float4 acc = make_float4(0.f,0.f,0.f,0.f);
    #pragma unroll
    for (int n=0;n<NCAM;n++){
        const float* L = sL + n*16;
        float c0 = L[0]*rx + L[1]*ry + L[2]*rz  + L[3];
        float c1 = L[4]*rx + L[5]*ry + L[6]*rz  + L[7];
        float hm = L[8]*rx + L[9]*ry + L[10]*rz + L[11];
        float z  = fmaxf(hm, EPSF);
        float u  = (c0 / z) / IMGW;
        float v  = (c1 / z) / IMGH;
        if (!(hm > EPSF && u > 0.f && u < 1.f && v > 0.f && v < 1.f)) continue;
        float x = u*(float)WF - 0.5f;
        float y = v*(float)HF - 0.5f;
        float x0f = floorf(x), y0f = floorf(y);
        float dx = x - x0f,    dy = y - y0f;
        int x0 = (int)x0f,     y0 = (int)y0f;
        float ws[4] = {(1.f-dx)*(1.f-dy), dx*(1.f-dy), (1.f-dx)*dy, dx*dy};
        int   xs[4] = {x0, x0+1, x0,   x0+1};
        int   ys[4] = {y0, y0,   y0+1, y0+1};
        const float* base = g_fmap + (size_t)n*HF*WF*CF;
        #pragma unroll
        for (int cr=0; cr<4; cr++){
            int xi = xs[cr], yi = ys[cr];
            if (xi >= 0 && xi < WF && yi >= 0 && yi < HF){
                float4 vq = reinterpret_cast<const float4*>(base + (yi*WF + xi)*CF)[lane];
                float wq = ws[cr];
                acc.x = fmaf(wq, vq.x, acc.x);
                acc.y = fmaf(wq, vq.y, acc.y);
                acc.z = fmaf(wq, vq.z, acc.z);
                acc.w = fmaf(wq, vq.w, acc.w);
            }
        }
    }
    reinterpret_cast<float4*>(g_x)[gw*32 + lane] = acc;
}

// ============================================================
// 2) PE layer 1 (3->256, relu) in fp32, split to bf16 hi/lo
//    rows indexed by qp = q*4+p (matches g_x [102400][128] view)
// ============================================================
__global__ void k_pe1(const float* __restrict__ bev, const float* __restrict__ w1,
                      const float* __restrict__ b1){
    int tid = threadIdx.x;
    int row = blockIdx.x*4 + (tid>>6);
    int j0  = (tid & 63) * 4;
    int q = row>>2, p = row&3;
    const float* bp = bev + (p*QQ + q)*3;
    float a0=bp[0], a1=bp[1], a2=bp[2];
    size_t o = (size_t)row*MIDW + j0;
    #pragma unroll
    for (int jj=0;jj<4;jj++){
        int j = j0+jj;
        float h = b1[j] + a0*w1[j] + a1*w1[MIDW+j] + a2*w1[2*MIDW+j];
        h = fmaxf(h,0.f);
        __nv_bfloat16 hh, hl;
        split2(h, hh, hl);
        g_h1h[o+jj] = hh;
        g_h1l[o+jj] = hl;
    }
}

// ============================================================
// weight split kernels
// ============================================================
__global__ void k_wsplit(const float* __restrict__ s, __nv_bfloat16* __restrict__ h,
                         __nv_bfloat16* __restrict__ l, int n){
    int i = blockIdx.x*256 + threadIdx.x;
    if (i < n) split2(s[i], h[i], l[i]);
}
// src [K=256][N] -> dst [n*256+k]
__global__ void k_wsplitT(const float* __restrict__ s, __nv_bfloat16* __restrict__ h,
                          __nv_bfloat16* __restrict__ l, int Nn){
    int i = blockIdx.x*256 + threadIdx.x;   // i = n*256 + k
    int k = i & 255, n_ = i >> 8;
    if (n_ < Nn) split2(s[k*Nn + n_], h[i], l[i]);
}
// g_x -> hi/lo
__global__ void k_splitx(){
    int i = blockIdx.x*256 + threadIdx.x;
    split2(g_x[i], g_xh[i], g_xl[i]);
}
// norm+gelu+split (y -> a)
template<int NCH>
__global__ void k_ngsplit(const float* __restrict__ y, const float* __restrict__ mean,
                          const float* __restrict__ inv,
                          __nv_bfloat16* __restrict__ ah, __nv_bfloat16* __restrict__ al){
    int i = blockIdx.x*256 + threadIdx.x;
    int c = i & (NCH-1);
    float v = (y[i] - mean[c]) * inv[c];
    v = gelu_f(v);
    split2(v, ah[i], al[i]);
}

// ============================================================
// 3) bf16x3 tensor-core GEMM.
//    C[m][n] = bias[n] + sum_k A[m][k]*W[n][k],  A = Ah+Al, W = Wh+Wl
//    Block tile 128x128xBK32, 8 warps (2m x 4n), warp tile 64x32.
//    EPI: 0 = fp32 [m][N]; 1 = relu+split bf16 [m][N];
//         2 = outF[m*N+n] += v;  3 = fp32 transposed [n][MROWS].
// ============================================================
#define LDK 40   // padded bf16 elems per smem row (80B, 16B-aligned)

__device__ __forceinline__ void ldsm4(uint32_t* r, uint32_t addr){
    asm volatile("ldmatrix.sync.aligned.m8n8.x4.shared.b16 {%0,%1,%2,%3}, [%4];"
        : "=r"(r[0]),"=r"(r[1]),"=r"(r[2]),"=r"(r[3]) : "r"(addr));
}
__device__ __forceinline__ void mma16816(float* d, const uint32_t* a, const uint32_t* b){
    asm volatile("mma.sync.aligned.m16n8k16.row.col.f32.bf16.bf16.f32 "
        "{%0,%1,%2,%3}, {%4,%5,%6,%7}, {%8,%9}, {%0,%1,%2,%3};"
        : "+f"(d[0]),"+f"(d[1]),"+f"(d[2]),"+f"(d[3])
        : "r"(a[0]),"r"(a[1]),"r"(a[2]),"r"(a[3]), "r"(b[0]),"r"(b[1]));
}

template<int K,int N,int EPI>
__global__ __launch_bounds__(256)
void k_mma(const __nv_bfloat16* __restrict__ Ah, const __nv_bfloat16* __restrict__ Al,
           const __nv_bfloat16* __restrict__ Wh, const __nv_bfloat16* __restrict__ Wl,
           const float* __restrict__ bias,
           float* __restrict__ outF, __nv_bfloat16* __restrict__ outH,
           __nv_bfloat16* __restrict__ outL)
{
    __shared__ __align__(16) __nv_bfloat16 sAh[128*LDK], sAl[128*LDK];
    __shared__ __align__(16) __nv_bfloat16 sWh[128*LDK], sWl[128*LDK];
    const int tid = threadIdx.x;
    const int m0 = blockIdx.x*128, n0 = blockIdx.y*128;
    const int lane = tid & 31, warp = tid >> 5;
    const int wm = warp & 1, wn = warp >> 1;

    float acc[4][4][4];
    #pragma unroll
    for(int i=0;i<4;i++)
        #pragma unroll
        for(int j=0;j<4;j++)
            #pragma unroll
            for(int v=0;v<4;v++) acc[i][j][v]=0.f;

    const uint32_t bAh = (uint32_t)__cvta_generic_to_shared(sAh);
    const uint32_t bAl = (uint32_t)__cvta_generic_to_shared(sAl);
    const uint32_t bWh = (uint32_t)__cvta_generic_to_shared(sWh);
    const uint32_t bWl = (uint32_t)__cvta_generic_to_shared(sWl);

    const int gr = tid >> 2;          // 0..63
    const int gc = (tid & 3) * 8;     // 0,8,16,24

    // ldmatrix element offsets (A: m16k16 x4-tile pattern; W: two n8 frags)
    const int aoff0 = (wm*64 + (lane & 15))*LDK + (lane >> 4)*8;
    const int woff0 = (wn*32 + ((lane >> 4) << 3) + (lane & 7))*LDK + ((lane >> 3) & 1)*8;

    for (int k0 = 0; k0 < K; k0 += 32){
        #pragma unroll
        for (int it=0; it<2; it++){
            int r = gr + it*64;
            const size_t ga = (size_t)(m0+r)*K + k0 + gc;
            const size_t gb = (size_t)(n0+r)*K + k0 + gc;
            *(uint4*)(sAh + r*LDK + gc) = *(const uint4*)(Ah + ga);
            *(uint4*)(sAl + r*LDK + gc) = *(const uint4*)(Al + ga);
            *(uint4*)(sWh + r*LDK + gc) = *(const uint4*)(Wh + gb);
            *(uint4*)(sWl + r*LDK + gc) = *(const uint4*)(Wl + gb);
        }
        __syncthreads();
        #pragma unroll
        for (int kk=0; kk<2; kk++){
            uint32_t bh[2][4], bl[2][4];
            #pragma unroll
            for (int np=0; np<2; np++){
                uint32_t off = (uint32_t)(woff0 + np*16*LDK + kk*16)*2;
                ldsm4(bh[np], bWh + off);
                ldsm4(bl[np], bWl + off);
            }
            #pragma unroll
            for (int mf=0; mf<4; mf++){
                uint32_t off = (uint32_t)(aoff0 + mf*16*LDK + kk*16)*2;
                uint32_t ah[4], al[4];
                ldsm4(ah, bAh + off);
                ldsm4(al, bAl + off);
                #pragma unroll
                for (int nf=0; nf<4; nf++){
                    const uint32_t* BH = &bh[nf>>1][(nf&1)*2];
                    const uint32_t* BL = &bl[nf>>1][(nf&1)*2];
                    mma16816(acc[mf][nf], ah, BH);
                    mma16816(acc[mf][nf], ah, BL);
                    mma16816(acc[mf][nf], al, BH);
                }
            }
        }
        __syncthreads();
    }

    const int er = m0 + wm*64 + (lane>>2);
    const int ec = n0 + wn*32 + (lane&3)*2;
    #pragma unroll
    for (int mf=0; mf<4; mf++){
        #pragma unroll
        for (int nf=0; nf<4; nf++){
            int c = ec + nf*8;
            float b0v = bias[c], b1v = bias[c+1];
            #pragma unroll
            for (int hh=0; hh<2; hh++){
                int r = er + mf*16 + hh*8;
                float v0 = acc[mf][nf][hh*2+0] + b0v;
                float v1 = acc[mf][nf][hh*2+1] + b1v;
                if (EPI == 0){
                    *(float2*)(outF + (size_t)r*N + c) = make_float2(v0, v1);
                } else if (EPI == 1){
                    v0 = fmaxf(v0, 0.f); v1 = fmaxf(v1, 0.f);
                    __nv_bfloat16 h0,l0,h1,l1;
                    split2(v0, h0, l0); split2(v1, h1, l1);
                    *(__nv_bfloat162*)(outH + (size_t)r*N + c) = __halves2bfloat162(h0, h1);
                    *(__nv_bfloat162*)(outL + (size_t)r*N + c) = __halves2bfloat162(l0, l1);
                } else if (EPI == 2){
                    float2* p = (float2*)(outF + (size_t)r*N + c);
                    float2 old = *p;
                    *p = make_float2(old.x + v0, old.y + v1);
                } else {
                    outF[(size_t)c*MROWS + r]     = v0;
                    outF[(size_t)(c+1)*MROWS + r] = v1;
                }
            }
        }
    }
}

// ============================================================
// 4) InstanceNorm stats
// ============================================================
template<int NCH>
__device__ __forceinline__ void stats_body(const float* __restrict__ Y,
                                           float* __restrict__ meanO, float* __restrict__ invO){
    int tid = threadIdx.x;
    int c   = blockIdx.x*8 + (tid & 7);
    int ml  = tid >> 3;
    float s = 0.f, s2 = 0.f;
    for (int m = ml; m < MROWS; m += 32){
        float v = Y[(size_t)m*NCH + c];
        s  += v;
        s2 = fmaf(v, v, s2);
    }
    __shared__ float ss[256], ss2[256];
    ss[tid] = s; ss2[tid] = s2;
    __syncthreads();
    #pragma unroll
    for (int st=128; st>=8; st>>=1){
        if (tid < st){ ss[tid]+=ss[tid+st]; ss2[tid]+=ss2[tid+st]; }
        __syncthreads();
    }
    if (tid < 8){
        float mean = ss[tid] / (float)MROWS;
        float var  = ss2[tid] / (float)MROWS - mean*mean;
        meanO[c] = mean;
        invO[c]  = rsqrtf(var + 1e-5f);
    }
}
__global__ void k_stats1(){ stats_body<KDIM>(g_y1, g_mean1, g_inv1); }
__global__ void k_stats2(){ stats_body<EDIM>(g_y2, g_mean2, g_inv2); }

// ============================================================
// host entry
// ============================================================
extern "C" void kernel_launch(void* const* d_in, const int* in_sizes, int n_in,
                              void* d_out, int out_size){
    const float* feat = (const float*)d_in[0];
    const float* l2i  = (const float*)d_in[1];
    const float* bev  = (const float*)d_in[2];
    const float* w1   = (const float*)d_in[3];
    const float* b1   = (const float*)d_in[4];
    const float* w2   = (const float*)d_in[5];
    const float* b2   = (const float*)d_in[6];
    const float* w3   = (const float*)d_in[7];
    const float* b3   = (const float*)d_in[8];
    const float* c1w  = (const float*)d_in[9];
    const float* c1b  = (const float*)d_in[10];
    const float* c2w  = (const float*)d_in[11];
    const float* c2b  = (const float*)d_in[12];
    const float* c3w  = (const float*)d_in[13];
    const float* c3b  = (const float*)d_in[14];
    float* out = (float*)d_out;

    // resolve device-global addresses on host
    __nv_bfloat16 *h1h, *h1l, *h2h, *h2l, *xh, *xl, *a2h, *a2l, *a3h, *a3l;
    __nv_bfloat16 *c1h, *c1l, *c2h, *c2l, *c3h, *c3l, *w2h, *w2l, *w3h, *w3l;
    float *y1p, *y2p, *xp, *m1, *i1, *m2, *i2;
    cudaGetSymbolAddress((void**)&h1h, g_h1h); cudaGetSymbolAddress((void**)&h1l, g_h1l);
    cudaGetSymbolAddress((void**)&h2h, g_h2h); cudaGetSymbolAddress((void**)&h2l, g_h2l);
    cudaGetSymbolAddress((void**)&xh,  g_xh ); cudaGetSymbolAddress((void**)&xl,  g_xl );
    cudaGetSymbolAddress((void**)&a2h, g_a2h); cudaGetSymbolAddress((void**)&a2l, g_a2l);
    cudaGetSymbolAddress((void**)&a3h, g_a3h); cudaGetSymbolAddress((void**)&a3l, g_a3l);
    cudaGetSymbolAddress((void**)&c1h, g_c1h); cudaGetSymbolAddress((void**)&c1l, g_c1l);
    cudaGetSymbolAddress((void**)&c2h, g_c2h); cudaGetSymbolAddress((void**)&c2l, g_c2l);
    cudaGetSymbolAddress((void**)&c3h, g_c3h); cudaGetSymbolAddress((void**)&c3l, g_c3l);
    cudaGetSymbolAddress((void**)&w2h, g_w2h); cudaGetSymbolAddress((void**)&w2l, g_w2l);
    cudaGetSymbolAddress((void**)&w3h, g_w3h); cudaGetSymbolAddress((void**)&w3l, g_w3l);
    cudaGetSymbolAddress((void**)&y1p, g_y1);  cudaGetSymbolAddress((void**)&y2p, g_y2);
    cudaGetSymbolAddress((void**)&xp,  g_x);
    cudaGetSymbolAddress((void**)&m1, g_mean1); cudaGetSymbolAddress((void**)&i1, g_inv1);
    cudaGetSymbolAddress((void**)&m2, g_mean2); cudaGetSymbolAddress((void**)&i2, g_inv2);

    // weight prep (tiny)
    k_wsplit <<<(KDIM*KDIM+255)/256, 256>>>(c1w, c1h, c1l, KDIM*KDIM);
    k_wsplit <<<(EDIM*KDIM+255)/256, 256>>>(c2w, c2h, c2l, EDIM*KDIM);
    k_wsplit <<<(EDIM*EDIM+255)/256, 256>>>(c3w, c3h, c3l, EDIM*EDIM);
    k_wsplitT<<<(MIDW*MIDW+255)/256, 256>>>(w2, w2h, w2l, MIDW);
    k_wsplitT<<<(EDIM*MIDW+255)/256, 256>>>(w3, w3h, w3l, EDIM);

    // sampling path
    k_transpose<<<(NCAM*HF*WF*CF + 255)/256, 256>>>(feat);
    k_sample  <<<(QQ*PP)/8, 256>>>(bev, l2i);

    // PE: layer1 (fp32) -> layer2 (mma, relu+split) -> layer3 (mma, += g_x)
    k_pe1<<<MR2/4, 256>>>(bev, w1, b1);
    k_mma<MIDW, MIDW, 1><<<dim3(MR2/128, MIDW/128), 256>>>(h1h, h1l, w2h, w2l, b2,
                                                           nullptr, h2h, h2l);
    k_mma<MIDW, EDIM, 2><<<dim3(MR2/128, 1), 256>>>(h2h, h2l, w3h, w3l, b3,
                                                    xp, nullptr, nullptr);

    // conv1
    k_splitx<<<MROWS*KDIM/256, 256>>>();
    k_mma<KDIM, KDIM, 0><<<dim3(MROWS/128, KDIM/128), 256>>>(xh, xl, c1h, c1l, c1b,
                                                             y1p, nullptr, nullptr);
    k_stats1<<<KDIM/8, 256>>>();
    k_ngsplit<KDIM><<<MROWS*KDIM/256, 256>>>(y1p, m1, i1, a2h, a2l);

    // conv2
    k_mma<KDIM, EDIM, 0><<<dim3(MROWS/128, 1), 256>>>(a2h, a2l, c2h, c2l, c2b,
                                                      y2p, nullptr, nullptr);
    k_stats2<<<EDIM/8, 256>>>();
    k_ngsplit<EDIM><<<MROWS*EDIM/256, 256>>>(y2p, m2, i2, a3h, a3l);

    // conv3 -> transposed output [E][Q]
    k_mma<EDIM, EDIM, 3><<<dim3(MROWS/128, 1), 256>>>(a3h, a3l, c3h, c3l, c3b,
                                                      out, nullptr, nullptr);
}